// round 13
// baseline (speedup 1.0000x reference)
#include <cuda_runtime.h>
#include <cstdint>

// ============================================================================
// DSPA via mma.sync tf32 — R12 pipelined structure + pair-permuted LDS.64
// fragment layouts with conflict-free strides (136/72 ≡ 8 mod 32):
//   x2 = dilated conv1d(x1); softmax over batch(2) => P = sigmoid(d),
//   d[n,j] = <Q[n], K'[j]>_128,  O[n,c2] = sum_j P[n,j] V[c2,j]
//   out[0,c,n] = x1 + O[n,c];  out[1,c,n] = x1 + S1[c] - O[n,64+c]
// ============================================================================

#define NN 4096
#define NC 128
#define NJ 4096
#define NSPLIT 4
#define JRANGE 1024
#define JSTEP 64
#define NSTEPS 16

__device__ __align__(256) float g_Kt[NJ * NC];          // K'[j][perm c2]
__device__ __align__(256) float g_V[NC * NJ];           // V[c2][perm j]
__device__ __align__(256) float g_Q[NN * NC];           // Q[n][perm c2]
__device__ __align__(256) float g_Op[NSPLIT * NC * NN]; // partial O [s][c2][n]
__device__ float g_S1[64];

// pair-interleave within 8-groups: logical col w -> stored (w&3)*2 + (w>>2).
// float2 at stored 2t then yields logical cols {t, t+4} = one mma k-pair.
__device__ __forceinline__ int perm8(int c) {
    return (c & ~7) | (((c & 3) << 1) | ((c >> 2) & 1));
}
__device__ __forceinline__ float tf32r(float x) {
    uint32_t r;
    asm("cvt.rna.tf32.f32 %0, %1;" : "=r"(r) : "f"(x));
    return __uint_as_float(r);
}
__device__ __forceinline__ float sigf(float x) {
    return __fdividef(1.0f, 1.0f + __expf(-x));
}
__device__ __forceinline__ void mma8(float* d, const uint32_t* a, uint32_t b0, uint32_t b1) {
    asm volatile(
        "mma.sync.aligned.m16n8k8.row.col.f32.tf32.tf32.f32 "
        "{%0,%1,%2,%3}, {%4,%5,%6,%7}, {%8,%9}, {%0,%1,%2,%3};"
        : "+f"(d[0]), "+f"(d[1]), "+f"(d[2]), "+f"(d[3])
        : "r"(a[0]), "r"(a[1]), "r"(a[2]), "r"(a[3]), "r"(b0), "r"(b1));
}
__device__ __forceinline__ uint32_t smem_u32(const void* p) {
    uint32_t a;
    asm("{ .reg .u64 t; cvta.to.shared.u64 t, %1; cvt.u32.u64 %0, t; }" : "=r"(a) : "l"(p));
    return a;
}
#define CP_ASYNC16(dst, src) \
    asm volatile("cp.async.cg.shared.global [%0], [%1], 16;" :: "r"(dst), "l"(src))
#define CP_COMMIT() asm volatile("cp.async.commit_group;" ::: "memory")
#define CP_WAIT0()  asm volatile("cp.async.wait_group 0;" ::: "memory")

// ---------------------------------------------------------------------------
// Kernel 1: dilated conv -> K'[j][perm c2], V[c2][perm j] + fused Q transpose
// grid 128 (32 j per block), block 512.
// ---------------------------------------------------------------------------
#define CONV_SMEM_BYTES ((64 * 195 + 128 * 37) * 4)
__global__ void __launch_bounds__(512) conv_kernel(const float* __restrict__ x,
                                                   const float* __restrict__ w,
                                                   const float* __restrict__ bias) {
    extern __shared__ float sm[];
    float* ws  = sm;             // [64][195]
    float* x1s = sm + 64 * 195;  // [128][37]

    const int tid = threadIdx.x;
    const int j0 = blockIdx.x * 32;

    for (int f = tid; f < 64 * 64 * 3; f += 512) {
        int co = f / 192, rem = f % 192;
        ws[co * 195 + rem] = w[f];
    }
    for (int f = tid; f < 128 * 36; f += 512) {
        int row = f / 36, p = f % 36;
        int pos = j0 - 1 + p;
        x1s[row * 37 + p] = (pos >= 0 && pos < NN) ? x[row * NN + pos] : 0.0f;
    }
    __syncthreads();

    // fused transpose: g_Q[n][perm c2] for n in [j0, j0+32)
    {
        const int c2q = tid & 127;
        const int c2qp = perm8(c2q);
#pragma unroll
        for (int i = 0; i < 8; i++) {
            int nn = (tid >> 7) + 4 * i;           // 0..31
            g_Q[(j0 + nn) * NC + c2qp] = tf32r(x1s[c2q * 37 + nn + 1]);
        }
    }

    const int c2 = tid & 127;
    const int grp = tid >> 7;
    const int bb = c2 >> 6, co = c2 & 63;
    const int base = grp * 8;
    float acc[8];
    float bv = bias[co];
#pragma unroll
    for (int jj = 0; jj < 8; jj++) acc[jj] = bv;

    for (int ci = 0; ci < 64; ci++) {
        float w0 = ws[co * 195 + ci * 3 + 0];
        float w1 = ws[co * 195 + ci * 3 + 1];
        float w2 = ws[co * 195 + ci * 3 + 2];
        const float* xr = &x1s[(bb * 64 + ci) * 37 + base];
#pragma unroll
        for (int jj = 0; jj < 8; jj++)
            acc[jj] += w0 * xr[jj] + w1 * xr[jj + 2] + w2 * xr[jj + 4];
    }

    const int c2p = perm8(c2);
#pragma unroll
    for (int jj = 0; jj < 8; jj++) {
        int j = j0 + base + jj;
        float v = (j < 4094) ? tf32r(acc[jj]) : 0.0f;   // zero-pad tail
        g_V[c2 * NJ + perm8(j)] = v;       // j permuted within its 8-group
        g_Kt[j * NC + c2p] = (c2 < 64) ? v : -v;
    }
}

// ---------------------------------------------------------------------------
// Kernel 2: S1[c] = sum over V row 64+c (perm & pad invariant)
// ---------------------------------------------------------------------------
__global__ void __launch_bounds__(256) s1_kernel() {
    __shared__ float red[256];
    const int c = blockIdx.x;
    float s = 0.0f;
    for (int j = threadIdx.x; j < 4096; j += 256) s += g_V[(64 + c) * NJ + j];
    red[threadIdx.x] = s;
    __syncthreads();
    for (int st = 128; st > 0; st >>= 1) {
        if (threadIdx.x < st) red[threadIdx.x] += red[threadIdx.x + st];
        __syncthreads();
    }
    if (threadIdx.x == 0) g_S1[c] = red[0];
}

// ---------------------------------------------------------------------------
// Kernel 3: main kernel. grid 128 = 32 m-tiles(128n) x 4 j-splits(1024 j).
// block 256 = 8 warps = 4m x 2n (G1 32n x 32j, G2 32n x 64c2 per warp).
// smem floats: Qs[128][136] | Ks[64][136] | Vs 2x[128][72] | Ps[128][72]
// (strides ≡8 mod 32 -> LDS.64 fragment loads conflict-free)
// Pipeline: [wait0;sync] G1; sigmoid; Pstore; [sync]; commit K(s+1),V(s+1); G2.
// ---------------------------------------------------------------------------
#define QS_F 0
#define KS_F 17408
#define VS0_F 26112
#define VS1_F 35328
#define PS_F 44544
#define TOT_F 53760
#define MAIN_SMEM_BYTES (TOT_F * 4)   // 215040

__global__ void __launch_bounds__(256, 1) dspa_main_kernel() {
    extern __shared__ float sm[];
    const uint32_t smb = smem_u32(sm);
    float* Qs = sm + QS_F;
    float* Ks = sm + KS_F;
    float* Ps = sm + PS_F;

    const int tid = threadIdx.x;
    const int warp = tid >> 5, lane = tid & 31;
    const int g = lane >> 2, t = lane & 3;
    const int wm = (warp & 3) * 32;
    const int wn1 = (warp >> 2) * 32;
    const int wn2 = (warp >> 2) * 64;
    const int m0 = (blockIdx.x & 31) << 7;
    const int split = blockIdx.x >> 5;
    const int jb0 = split * JRANGE;

    // in-group storage columns for P writes (logical cols 2t, 2t+1)
    const int pc0 = (((2 * t) & 3) << 1) | ((2 * t) >> 2);
    const int pc1 = (((2 * t + 1) & 3) << 1) | ((2 * t + 1) >> 2);

    // ---- prologue: cp.async K(0), V(0); stage Qs; wait; sync ----
#pragma unroll
    for (int i = 0; i < 8; i++) {
        int c = tid + 256 * i;                 // K: 64 rows x 32 float4 chunks
        int row = c >> 5, off = c & 31;
        CP_ASYNC16(smb + KS_F * 4 + row * (136 * 4) + off * 16,
                   (const void*)&g_Kt[(jb0 + row) * NC + off * 4]);
    }
    CP_COMMIT();
#pragma unroll
    for (int i = 0; i < 8; i++) {
        int c = tid + 256 * i;                 // V: 128 rows x 16 chunks
        int row = c >> 4, off = c & 15;
        CP_ASYNC16(smb + VS0_F * 4 + row * (72 * 4) + off * 16,
                   (const void*)&g_V[row * NJ + jb0 + off * 4]);
    }
    CP_COMMIT();
#pragma unroll
    for (int it = 0; it < 16; it++) {
        int idx = it * 256 + tid;              // Q: 128 rows x 32 chunks
        int r = idx >> 5, q = idx & 31;
        float4 v = *reinterpret_cast<const float4*>(&g_Q[(m0 + r) * NC + 4 * q]);
        *reinterpret_cast<float4*>(&Qs[r * 136 + 4 * q]) = v;
    }

    float acc2[16][4];
#pragma unroll
    for (int i = 0; i < 16; i++)
#pragma unroll
        for (int k = 0; k < 4; k++) acc2[i][k] = 0.0f;

    for (int s = 0; s < NSTEPS; s++) {
        float* Vs = sm + ((s & 1) ? VS1_F : VS0_F);

        CP_WAIT0();          // K(s), V(s) arrived
        __syncthreads();     // and G2(s-1) done reading V(s-1)/P(s-1)

        // ---- GEMM1: warp computes d[32n x 32j] over c2=128 ----
        float acc1[8][4];
#pragma unroll
        for (int i = 0; i < 8; i++)
#pragma unroll
            for (int k = 0; k < 4; k++) acc1[i][k] = 0.0f;

#pragma unroll
        for (int k0 = 0; k0 < 128; k0 += 8) {
            uint32_t a[2][4];
#pragma unroll
            for (int mt = 0; mt < 2; mt++) {
                float2 q0 = *reinterpret_cast<const float2*>(
                    &Qs[(wm + mt * 16 + g) * 136 + k0 + 2 * t]);
                float2 q1 = *reinterpret_cast<const float2*>(
                    &Qs[(wm + mt * 16 + g + 8) * 136 + k0 + 2 * t]);
                a[mt][0] = __float_as_uint(q0.x); a[mt][1] = __float_as_uint(q1.x);
                a[mt][2] = __float_as_uint(q0.y); a[mt][3] = __float_as_uint(q1.y);
            }
#pragma unroll
            for (int nt = 0; nt < 4; nt++) {
                float2 b = *reinterpret_cast<const float2*>(
                    &Ks[(wn1 + nt * 8 + g) * 136 + k0 + 2 * t]);
                uint32_t b0 = __float_as_uint(b.x);
                uint32_t b1 = __float_as_uint(b.y);
#pragma unroll
                for (int mt = 0; mt < 2; mt++)
                    mma8(acc1[mt * 4 + nt], a[mt], b0, b1);
            }
        }

        // sigmoid + store P at pair-permuted positions
#pragma unroll
        for (int mt = 0; mt < 2; mt++)
#pragma unroll
            for (int nt = 0; nt < 4; nt++) {
                int rn = wm + mt * 16 + g;
                int cb = wn1 + nt * 8;
                float* c = acc1[mt * 4 + nt];
                Ps[rn * 72 + cb + pc0]       = tf32r(sigf(c[0]));
                Ps[rn * 72 + cb + pc1]       = tf32r(sigf(c[1]));
                Ps[(rn + 8) * 72 + cb + pc0] = tf32r(sigf(c[2]));
                Ps[(rn + 8) * 72 + cb + pc1] = tf32r(sigf(c[3]));
            }
        __syncthreads();     // P visible; G1 reads of Ks done

        // prefetch K(s+1) (single buffer) and V(s+1) (other buffer)
        if (s + 1 < NSTEPS) {
            const int jb = jb0 + (s + 1) * JSTEP;
            uint32_t vdst = smb + (((s + 1) & 1) ? VS1_F : VS0_F) * 4;
#pragma unroll
            for (int i = 0; i < 8; i++) {
                int c = tid + 256 * i;
                int row = c >> 5, off = c & 31;
                CP_ASYNC16(smb + KS_F * 4 + row * (136 * 4) + off * 16,
                           (const void*)&g_Kt[(jb + row) * NC + off * 4]);
            }
            CP_COMMIT();
#pragma unroll
            for (int i = 0; i < 8; i++) {
                int c = tid + 256 * i;
                int row = c >> 4, off = c & 15;
                CP_ASYNC16(vdst + row * (72 * 4) + off * 16,
                           (const void*)&g_V[row * NJ + jb + off * 4]);
            }
            CP_COMMIT();
        }

        // ---- GEMM2: warp accumulates O[32n x 64c2] over j=64 ----
#pragma unroll
        for (int k0 = 0; k0 < 64; k0 += 8) {
            uint32_t a[2][4];
#pragma unroll
            for (int mt = 0; mt < 2; mt++) {
                float2 p0 = *reinterpret_cast<const float2*>(
                    &Ps[(wm + mt * 16 + g) * 72 + k0 + 2 * t]);
                float2 p1 = *reinterpret_cast<const float2*>(
                    &Ps[(wm + mt * 16 + g + 8) * 72 + k0 + 2 * t]);
                a[mt][0] = __float_as_uint(p0.x); a[mt][1] = __float_as_uint(p1.x);
                a[mt][2] = __float_as_uint(p0.y); a[mt][3] = __float_as_uint(p1.y);
            }
#pragma unroll
            for (int nt = 0; nt < 8; nt++) {
                float2 b = *reinterpret_cast<const float2*>(
                    &Vs[(wn2 + nt * 8 + g) * 72 + k0 + 2 * t]);
                uint32_t b0 = __float_as_uint(b.x);
                uint32_t b1 = __float_as_uint(b.y);
#pragma unroll
                for (int mt = 0; mt < 2; mt++)
                    mma8(acc2[mt * 8 + nt], a[mt], b0, b1);
            }
        }
    }

    // ---- epilogue: fragments -> smem [c2][n] -> coalesced partial stores ----
    __syncthreads();
    float* Osm = sm;   // [128][129] floats, reuses Qs region
#pragma unroll
    for (int mt = 0; mt < 2; mt++)
#pragma unroll
        for (int nt = 0; nt < 8; nt++) {
            int n = wm + mt * 16 + g;
            int c2 = wn2 + nt * 8 + 2 * t;
            const float* c = acc2[mt * 8 + nt];
            Osm[c2 * 129 + n]           = c[0];
            Osm[(c2 + 1) * 129 + n]     = c[1];
            Osm[c2 * 129 + n + 8]       = c[2];
            Osm[(c2 + 1) * 129 + n + 8] = c[3];
        }
    __syncthreads();
#pragma unroll
    for (int it = 0; it < 16; it++) {
        int idx = it * 256 + tid;
        int r = idx >> 5, q = idx & 31;
        float4 v = make_float4(Osm[r * 129 + 4 * q], Osm[r * 129 + 4 * q + 1],
                               Osm[r * 129 + 4 * q + 2], Osm[r * 129 + 4 * q + 3]);
        *reinterpret_cast<float4*>(&g_Op[((split << 7) + r) * NN + m0 + 4 * q]) = v;
    }
}

// ---------------------------------------------------------------------------
// Kernel 4: combine partials + residual + S1 -> out [c2][n]
// ---------------------------------------------------------------------------
__global__ void __launch_bounds__(256) reduce_kernel(const float* __restrict__ x,
                                                     float* __restrict__ out) {
    int idx = blockIdx.x * 256 + threadIdx.x;   // float4 units
    int c2 = idx >> 10;
    const float4* x4 = reinterpret_cast<const float4*>(x);
    const float4* o4 = reinterpret_cast<const float4*>(g_Op);
    float4 xv = x4[idx];
    float4 s = make_float4(0.f, 0.f, 0.f, 0.f);
#pragma unroll
    for (int sp = 0; sp < NSPLIT; sp++) {
        float4 v = o4[((sp << 7) + c2) * (NN / 4) + (idx & 1023)];
        s.x += v.x; s.y += v.y; s.z += v.z; s.w += v.w;
    }
    float4 r;
    if (c2 < 64) {
        r.x = xv.x + s.x; r.y = xv.y + s.y; r.z = xv.z + s.z; r.w = xv.w + s.w;
    } else {
        float b = g_S1[c2 - 64];
        r.x = xv.x + b - s.x; r.y = xv.y + b - s.y;
        r.z = xv.z + b - s.z; r.w = xv.w + b - s.w;
    }
    reinterpret_cast<float4*>(out)[idx] = r;
}

// ---------------------------------------------------------------------------
extern "C" void kernel_launch(void* const* d_in, const int* in_sizes, int n_in,
                              void* d_out, int out_size) {
    const float* x  = (const float*)d_in[0];   // [2,64,16,16,16] = [128][4096]
    const float* cw = (const float*)d_in[1];   // [64,64,3]
    const float* cb = (const float*)d_in[2];   // [64]
    float* out = (float*)d_out;

    cudaFuncSetAttribute(conv_kernel, cudaFuncAttributeMaxDynamicSharedMemorySize, CONV_SMEM_BYTES);
    cudaFuncSetAttribute(dspa_main_kernel, cudaFuncAttributeMaxDynamicSharedMemorySize, MAIN_SMEM_BYTES);

    conv_kernel<<<128, 512, CONV_SMEM_BYTES>>>(x, cw, cb);
    s1_kernel<<<64, 256>>>();
    dspa_main_kernel<<<128, 256, MAIN_SMEM_BYTES>>>();
    reduce_kernel<<<512, 256>>>(x, out);
}

// round 14
// speedup vs baseline: 1.0776x; 1.0776x over previous
#include <cuda_runtime.h>
#include <cstdint>

// ============================================================================
// DSPA via mma.sync tf32 — R12 structure verbatim (proven fastest) with:
//   * sigmoid via tanh.approx (1 MUFU instead of 2)
//   * high-MLP reduce kernel
//   x2 = dilated conv1d(x1); softmax over batch(2) => P = sigmoid(d),
//   d[n,j] = <Q[n], K'[j]>_128,  O[n,c2] = sum_j P[n,j] V[c2,j]
//   out[0,c,n] = x1 + O[n,c];  out[1,c,n] = x1 + S1[c] - O[n,64+c]
// ============================================================================

#define NN 4096
#define NC 128
#define NJ 4096
#define NSPLIT 4
#define JRANGE 1024
#define JSTEP 64
#define NSTEPS 16

__device__ __align__(256) float g_Kt[NJ * NC];          // K'[j][c2]
__device__ __align__(256) float g_V[NC * NJ];           // V[c2][j]
__device__ __align__(256) float g_Q[NN * NC];           // Q[n][c2]
__device__ __align__(256) float g_Op[NSPLIT * NC * NN]; // partial O [s][c2][n]
__device__ float g_S1[64];

__device__ __forceinline__ float tf32r(float x) {
    uint32_t r;
    asm("cvt.rna.tf32.f32 %0, %1;" : "=r"(r) : "f"(x));
    return __uint_as_float(r);
}
// sigmoid(x) = 0.5*tanh(x/2) + 0.5  (single MUFU)
__device__ __forceinline__ float sigf(float x) {
    float th;
    asm("tanh.approx.f32 %0, %1;" : "=f"(th) : "f"(0.5f * x));
    return fmaf(0.5f, th, 0.5f);
}
__device__ __forceinline__ void mma8(float* d, const uint32_t* a, uint32_t b0, uint32_t b1) {
    asm volatile(
        "mma.sync.aligned.m16n8k8.row.col.f32.tf32.tf32.f32 "
        "{%0,%1,%2,%3}, {%4,%5,%6,%7}, {%8,%9}, {%0,%1,%2,%3};"
        : "+f"(d[0]), "+f"(d[1]), "+f"(d[2]), "+f"(d[3])
        : "r"(a[0]), "r"(a[1]), "r"(a[2]), "r"(a[3]), "r"(b0), "r"(b1));
}
__device__ __forceinline__ uint32_t smem_u32(const void* p) {
    uint32_t a;
    asm("{ .reg .u64 t; cvta.to.shared.u64 t, %1; cvt.u32.u64 %0, t; }" : "=r"(a) : "l"(p));
    return a;
}
#define CP_ASYNC16(dst, src) \
    asm volatile("cp.async.cg.shared.global [%0], [%1], 16;" :: "r"(dst), "l"(src))
#define CP_COMMIT() asm volatile("cp.async.commit_group;" ::: "memory")
#define CP_WAIT0()  asm volatile("cp.async.wait_group 0;" ::: "memory")

// ---------------------------------------------------------------------------
// Kernel 1: dilated conv -> K'[j][c2], V[c2][j] + fused Q transpose
// grid 128 (32 j per block), block 512.
// ---------------------------------------------------------------------------
#define CONV_SMEM_BYTES ((64 * 195 + 128 * 37) * 4)
__global__ void __launch_bounds__(512) conv_kernel(const float* __restrict__ x,
                                                   const float* __restrict__ w,
                                                   const float* __restrict__ bias) {
    extern __shared__ float sm[];
    float* ws  = sm;             // [64][195]
    float* x1s = sm + 64 * 195;  // [128][37]

    const int tid = threadIdx.x;
    const int j0 = blockIdx.x * 32;

    for (int f = tid; f < 64 * 64 * 3; f += 512) {
        int co = f / 192, rem = f % 192;
        ws[co * 195 + rem] = w[f];
    }
    for (int f = tid; f < 128 * 36; f += 512) {
        int row = f / 36, p = f % 36;
        int pos = j0 - 1 + p;
        x1s[row * 37 + p] = (pos >= 0 && pos < NN) ? x[row * NN + pos] : 0.0f;
    }
    __syncthreads();

    // fused transpose: g_Q[n][c2] for n in [j0, j0+32) from staged x1s
    {
        const int c2q = tid & 127;
#pragma unroll
        for (int i = 0; i < 8; i++) {
            int nn = (tid >> 7) + 4 * i;           // 0..31
            g_Q[(j0 + nn) * NC + c2q] = tf32r(x1s[c2q * 37 + nn + 1]);
        }
    }

    const int c2 = tid & 127;
    const int grp = tid >> 7;
    const int bb = c2 >> 6, co = c2 & 63;
    const int base = grp * 8;
    float acc[8];
    float bv = bias[co];
#pragma unroll
    for (int jj = 0; jj < 8; jj++) acc[jj] = bv;

    for (int ci = 0; ci < 64; ci++) {
        float w0 = ws[co * 195 + ci * 3 + 0];
        float w1 = ws[co * 195 + ci * 3 + 1];
        float w2 = ws[co * 195 + ci * 3 + 2];
        const float* xr = &x1s[(bb * 64 + ci) * 37 + base];
#pragma unroll
        for (int jj = 0; jj < 8; jj++)
            acc[jj] += w0 * xr[jj] + w1 * xr[jj + 2] + w2 * xr[jj + 4];
    }

#pragma unroll
    for (int jj = 0; jj < 8; jj++) {
        int j = j0 + base + jj;
        float v = (j < 4094) ? tf32r(acc[jj]) : 0.0f;   // zero-pad tail
        g_V[c2 * NJ + j] = v;
        g_Kt[j * NC + c2] = (c2 < 64) ? v : -v;
    }
}

// ---------------------------------------------------------------------------
// Kernel 2: S1[c] = sum over V row 64+c (pad entries are zero)
// ---------------------------------------------------------------------------
__global__ void __launch_bounds__(256) s1_kernel() {
    __shared__ float red[256];
    const int c = blockIdx.x;
    float s = 0.0f;
    for (int j = threadIdx.x; j < 4096; j += 256) s += g_V[(64 + c) * NJ + j];
    red[threadIdx.x] = s;
    __syncthreads();
    for (int st = 128; st > 0; st >>= 1) {
        if (threadIdx.x < st) red[threadIdx.x] += red[threadIdx.x + st];
        __syncthreads();
    }
    if (threadIdx.x == 0) g_S1[c] = red[0];
}

// ---------------------------------------------------------------------------
// Kernel 3: main kernel. grid 128 = 32 m-tiles(128n) x 4 j-splits(1024 j).
// block 256 = 8 warps = 4m x 2n (G1 32n x 32j, G2 32n x 64c2 per warp).
// smem floats: Qs[128][132] | Ks[64][132] | Vs 2x[128][68] | Ps[128][68]
// Pipeline: [wait0;sync] G1; sigmoid; Pstore; [sync]; commit K(s+1),V(s+1);
// G2.  K single-buffered, V double-buffered.
// ---------------------------------------------------------------------------
#define QS_F 0
#define KS_F 16896
#define VS0_F 25344
#define VS1_F 34048
#define PS_F 42752
#define TOT_F 51456
#define MAIN_SMEM_BYTES (TOT_F * 4)   // 205824

__global__ void __launch_bounds__(256, 1) dspa_main_kernel() {
    extern __shared__ float sm[];
    const uint32_t smb = smem_u32(sm);
    float* Qs = sm + QS_F;
    float* Ks = sm + KS_F;
    float* Ps = sm + PS_F;

    const int tid = threadIdx.x;
    const int warp = tid >> 5, lane = tid & 31;
    const int g = lane >> 2, t = lane & 3;
    const int wm = (warp & 3) * 32;
    const int wn1 = (warp >> 2) * 32;
    const int wn2 = (warp >> 2) * 64;
    const int m0 = (blockIdx.x & 31) << 7;
    const int split = blockIdx.x >> 5;
    const int jb0 = split * JRANGE;

    // ---- prologue: cp.async K(0), V(0); stage Qs; wait; sync ----
#pragma unroll
    for (int i = 0; i < 8; i++) {
        int c = tid + 256 * i;                 // K: 64 rows x 32 float4 chunks
        int row = c >> 5, off = c & 31;
        CP_ASYNC16(smb + KS_F * 4 + row * (132 * 4) + off * 16,
                   (const void*)&g_Kt[(jb0 + row) * NC + off * 4]);
    }
    CP_COMMIT();
#pragma unroll
    for (int i = 0; i < 8; i++) {
        int c = tid + 256 * i;                 // V: 128 rows x 16 chunks
        int row = c >> 4, off = c & 15;
        CP_ASYNC16(smb + VS0_F * 4 + row * (68 * 4) + off * 16,
                   (const void*)&g_V[row * NJ + jb0 + off * 4]);
    }
    CP_COMMIT();
#pragma unroll
    for (int it = 0; it < 16; it++) {
        int idx = it * 256 + tid;              // Q: 128 rows x 32 chunks
        int r = idx >> 5, q = idx & 31;
        float4 v = *reinterpret_cast<const float4*>(&g_Q[(m0 + r) * NC + 4 * q]);
        *reinterpret_cast<float4*>(&Qs[r * 132 + 4 * q]) = v;
    }

    float acc2[16][4];
#pragma unroll
    for (int i = 0; i < 16; i++)
#pragma unroll
        for (int k = 0; k < 4; k++) acc2[i][k] = 0.0f;

    for (int s = 0; s < NSTEPS; s++) {
        float* Vs = sm + ((s & 1) ? VS1_F : VS0_F);

        CP_WAIT0();          // K(s) and V(s) (committed last step) arrived
        __syncthreads();     // also: G2(s-1) done reading V(s-1)/P(s-1)

        // ---- GEMM1: warp computes d[32n x 32j] over c2=128 ----
        float acc1[8][4];
#pragma unroll
        for (int i = 0; i < 8; i++)
#pragma unroll
            for (int k = 0; k < 4; k++) acc1[i][k] = 0.0f;

#pragma unroll
        for (int k0 = 0; k0 < 128; k0 += 8) {
            uint32_t a[2][4];
#pragma unroll
            for (int mt = 0; mt < 2; mt++) {
                const float* q0 = &Qs[(wm + mt * 16 + g) * 132 + k0 + t];
                const float* q1 = q0 + 8 * 132;
                a[mt][0] = __float_as_uint(q0[0]);
                a[mt][1] = __float_as_uint(q1[0]);
                a[mt][2] = __float_as_uint(q0[4]);
                a[mt][3] = __float_as_uint(q1[4]);
            }
#pragma unroll
            for (int nt = 0; nt < 4; nt++) {
                const float* kp = &Ks[(wn1 + nt * 8 + g) * 132 + k0 + t];
                uint32_t b0 = __float_as_uint(kp[0]);
                uint32_t b1 = __float_as_uint(kp[4]);
#pragma unroll
                for (int mt = 0; mt < 2; mt++)
                    mma8(acc1[mt * 4 + nt], a[mt], b0, b1);
            }
        }

        // sigmoid + store P
#pragma unroll
        for (int mt = 0; mt < 2; mt++)
#pragma unroll
            for (int nt = 0; nt < 4; nt++) {
                int rn = wm + mt * 16 + g;
                int cj = wn1 + nt * 8 + 2 * t;
                float* c = acc1[mt * 4 + nt];
                Ps[rn * 68 + cj]           = tf32r(sigf(c[0]));
                Ps[rn * 68 + cj + 1]       = tf32r(sigf(c[1]));
                Ps[(rn + 8) * 68 + cj]     = tf32r(sigf(c[2]));
                Ps[(rn + 8) * 68 + cj + 1] = tf32r(sigf(c[3]));
            }
        __syncthreads();     // P visible; all G1 reads of Ks done

        // prefetch K(s+1) (single buffer, safe now) and V(s+1) (other buffer)
        if (s + 1 < NSTEPS) {
            const int jb = jb0 + (s + 1) * JSTEP;
            uint32_t vdst = smb + (((s + 1) & 1) ? VS1_F : VS0_F) * 4;
#pragma unroll
            for (int i = 0; i < 8; i++) {
                int c = tid + 256 * i;
                int row = c >> 5, off = c & 31;
                CP_ASYNC16(smb + KS_F * 4 + row * (132 * 4) + off * 16,
                           (const void*)&g_Kt[(jb + row) * NC + off * 4]);
            }
            CP_COMMIT();
#pragma unroll
            for (int i = 0; i < 8; i++) {
                int c = tid + 256 * i;
                int row = c >> 4, off = c & 15;
                CP_ASYNC16(vdst + row * (68 * 4) + off * 16,
                           (const void*)&g_V[row * NJ + jb + off * 4]);
            }
            CP_COMMIT();
        }

        // ---- GEMM2: warp accumulates O[32n x 64c2] over j=64 ----
#pragma unroll
        for (int k0 = 0; k0 < 64; k0 += 8) {
            uint32_t a[2][4];
#pragma unroll
            for (int mt = 0; mt < 2; mt++) {
                const float* p0 = &Ps[(wm + mt * 16 + g) * 68 + k0 + t];
                const float* p1 = p0 + 8 * 68;
                a[mt][0] = __float_as_uint(p0[0]);
                a[mt][1] = __float_as_uint(p1[0]);
                a[mt][2] = __float_as_uint(p0[4]);
                a[mt][3] = __float_as_uint(p1[4]);
            }
#pragma unroll
            for (int nt = 0; nt < 8; nt++) {
                const float* vp = &Vs[(wn2 + nt * 8 + g) * 68 + k0 + t];
                uint32_t b0 = __float_as_uint(vp[0]);
                uint32_t b1 = __float_as_uint(vp[4]);
#pragma unroll
                for (int mt = 0; mt < 2; mt++)
                    mma8(acc2[mt * 8 + nt], a[mt], b0, b1);
            }
        }
    }

    // ---- epilogue: fragments -> smem [c2][n] -> coalesced partial stores ----
    __syncthreads();
    float* Osm = sm;   // [128][129] floats, reuses Qs region
#pragma unroll
    for (int mt = 0; mt < 2; mt++)
#pragma unroll
        for (int nt = 0; nt < 8; nt++) {
            int n = wm + mt * 16 + g;
            int c2 = wn2 + nt * 8 + 2 * t;
            const float* c = acc2[mt * 8 + nt];
            Osm[c2 * 129 + n]           = c[0];
            Osm[(c2 + 1) * 129 + n]     = c[1];
            Osm[c2 * 129 + n + 8]       = c[2];
            Osm[(c2 + 1) * 129 + n + 8] = c[3];
        }
    __syncthreads();
#pragma unroll
    for (int it = 0; it < 16; it++) {
        int idx = it * 256 + tid;
        int r = idx >> 5, q = idx & 31;
        float4 v = make_float4(Osm[r * 129 + 4 * q], Osm[r * 129 + 4 * q + 1],
                               Osm[r * 129 + 4 * q + 2], Osm[r * 129 + 4 * q + 3]);
        *reinterpret_cast<float4*>(&g_Op[((split << 7) + r) * NN + m0 + 4 * q]) = v;
    }
}

// ---------------------------------------------------------------------------
// Kernel 4: combine partials + residual + S1 -> out [c2][n]
// grid 128, block 256; 4 outputs/thread, all loads batched for MLP.
// ---------------------------------------------------------------------------
__global__ void __launch_bounds__(256) reduce_kernel(const float* __restrict__ x,
                                                     float* __restrict__ out) {
    const float4* x4 = reinterpret_cast<const float4*>(x);
    const float4* o4 = reinterpret_cast<const float4*>(g_Op);
    int base = blockIdx.x * 256 + threadIdx.x;   // float4 units

    float4 xv[4], pv[4][NSPLIT];
#pragma unroll
    for (int u = 0; u < 4; u++) {
        int idx = base + u * 32768;
        int c2 = idx >> 10;
        xv[u] = __ldcg(&x4[idx]);
#pragma unroll
        for (int sp = 0; sp < NSPLIT; sp++)
            pv[u][sp] = __ldcg(&o4[((sp << 7) + c2) * (NN / 4) + (idx & 1023)]);
    }
#pragma unroll
    for (int u = 0; u < 4; u++) {
        int idx = base + u * 32768;
        int c2 = idx >> 10;
        float4 s = make_float4(0.f, 0.f, 0.f, 0.f);
#pragma unroll
        for (int sp = 0; sp < NSPLIT; sp++) {
            s.x += pv[u][sp].x; s.y += pv[u][sp].y;
            s.z += pv[u][sp].z; s.w += pv[u][sp].w;
        }
        float4 r;
        if (c2 < 64) {
            r.x = xv[u].x + s.x; r.y = xv[u].y + s.y;
            r.z = xv[u].z + s.z; r.w = xv[u].w + s.w;
        } else {
            float b = g_S1[c2 - 64];
            r.x = xv[u].x + b - s.x; r.y = xv[u].y + b - s.y;
            r.z = xv[u].z + b - s.z; r.w = xv[u].w + b - s.w;
        }
        reinterpret_cast<float4*>(out)[idx] = r;
    }
}

// ---------------------------------------------------------------------------
extern "C" void kernel_launch(void* const* d_in, const int* in_sizes, int n_in,
                              void* d_out, int out_size) {
    const float* x  = (const float*)d_in[0];   // [2,64,16,16,16] = [128][4096]
    const float* cw = (const float*)d_in[1];   // [64,64,3]
    const float* cb = (const float*)d_in[2];   // [64]
    float* out = (float*)d_out;

    cudaFuncSetAttribute(conv_kernel, cudaFuncAttributeMaxDynamicSharedMemorySize, CONV_SMEM_BYTES);
    cudaFuncSetAttribute(dspa_main_kernel, cudaFuncAttributeMaxDynamicSharedMemorySize, MAIN_SMEM_BYTES);

    conv_kernel<<<128, 512, CONV_SMEM_BYTES>>>(x, cw, cb);
    s1_kernel<<<64, 256>>>();
    dspa_main_kernel<<<128, 256, MAIN_SMEM_BYTES>>>();
    reduce_kernel<<<128, 256>>>(x, out);
}

// round 16
// speedup vs baseline: 1.6130x; 1.4968x over previous
#include <cuda_runtime.h>
#include <cstdint>

// ============================================================================
// DSPA via mma.sync tf32 — R12 champion, byte-for-byte (90.8 us):
//   x2 = dilated conv1d(x1); softmax over batch(2) => P = sigmoid(d),
//   d[n,j] = <Q[n], K'[j]>_128,  O[n,c2] = sum_j P[n,j] V[c2,j]
//   out[0,c,n] = x1 + O[n,c];  out[1,c,n] = x1 + S1[c] - O[n,64+c]
// ============================================================================

#define NN 4096
#define NC 128
#define NJ 4096
#define NSPLIT 4
#define JRANGE 1024
#define JSTEP 64
#define NSTEPS 16

__device__ __align__(256) float g_Kt[NJ * NC];          // K'[j][c2]
__device__ __align__(256) float g_V[NC * NJ];           // V[c2][j]
__device__ __align__(256) float g_Q[NN * NC];           // Q[n][c2]
__device__ __align__(256) float g_Op[NSPLIT * NC * NN]; // partial O [s][c2][n]
__device__ float g_S1[64];

__device__ __forceinline__ float tf32r(float x) {
    uint32_t r;
    asm("cvt.rna.tf32.f32 %0, %1;" : "=r"(r) : "f"(x));
    return __uint_as_float(r);
}
__device__ __forceinline__ float sigf(float x) {
    return __fdividef(1.0f, 1.0f + __expf(-x));
}
__device__ __forceinline__ void mma8(float* d, const uint32_t* a, uint32_t b0, uint32_t b1) {
    asm volatile(
        "mma.sync.aligned.m16n8k8.row.col.f32.tf32.tf32.f32 "
        "{%0,%1,%2,%3}, {%4,%5,%6,%7}, {%8,%9}, {%0,%1,%2,%3};"
        : "+f"(d[0]), "+f"(d[1]), "+f"(d[2]), "+f"(d[3])
        : "r"(a[0]), "r"(a[1]), "r"(a[2]), "r"(a[3]), "r"(b0), "r"(b1));
}
__device__ __forceinline__ uint32_t smem_u32(const void* p) {
    uint32_t a;
    asm("{ .reg .u64 t; cvta.to.shared.u64 t, %1; cvt.u32.u64 %0, t; }" : "=r"(a) : "l"(p));
    return a;
}
#define CP_ASYNC16(dst, src) \
    asm volatile("cp.async.cg.shared.global [%0], [%1], 16;" :: "r"(dst), "l"(src))
#define CP_COMMIT() asm volatile("cp.async.commit_group;" ::: "memory")
#define CP_WAIT0()  asm volatile("cp.async.wait_group 0;" ::: "memory")

// ---------------------------------------------------------------------------
// Kernel 1: dilated conv -> K'[j][c2], V[c2][j] + fused Q transpose
// grid 128 (32 j per block), block 512.
// ---------------------------------------------------------------------------
#define CONV_SMEM_BYTES ((64 * 195 + 128 * 37) * 4)
__global__ void __launch_bounds__(512) conv_kernel(const float* __restrict__ x,
                                                   const float* __restrict__ w,
                                                   const float* __restrict__ bias) {
    extern __shared__ float sm[];
    float* ws  = sm;             // [64][195]
    float* x1s = sm + 64 * 195;  // [128][37]

    const int tid = threadIdx.x;
    const int j0 = blockIdx.x * 32;

    for (int f = tid; f < 64 * 64 * 3; f += 512) {
        int co = f / 192, rem = f % 192;
        ws[co * 195 + rem] = w[f];
    }
    for (int f = tid; f < 128 * 36; f += 512) {
        int row = f / 36, p = f % 36;
        int pos = j0 - 1 + p;
        x1s[row * 37 + p] = (pos >= 0 && pos < NN) ? x[row * NN + pos] : 0.0f;
    }
    __syncthreads();

    // fused transpose: g_Q[n][c2] for n in [j0, j0+32) from staged x1s
    {
        const int c2q = tid & 127;
#pragma unroll
        for (int i = 0; i < 8; i++) {
            int nn = (tid >> 7) + 4 * i;           // 0..31
            g_Q[(j0 + nn) * NC + c2q] = tf32r(x1s[c2q * 37 + nn + 1]);
        }
    }

    const int c2 = tid & 127;
    const int grp = tid >> 7;
    const int bb = c2 >> 6, co = c2 & 63;
    const int base = grp * 8;
    float acc[8];
    float bv = bias[co];
#pragma unroll
    for (int jj = 0; jj < 8; jj++) acc[jj] = bv;

    for (int ci = 0; ci < 64; ci++) {
        float w0 = ws[co * 195 + ci * 3 + 0];
        float w1 = ws[co * 195 + ci * 3 + 1];
        float w2 = ws[co * 195 + ci * 3 + 2];
        const float* xr = &x1s[(bb * 64 + ci) * 37 + base];
#pragma unroll
        for (int jj = 0; jj < 8; jj++)
            acc[jj] += w0 * xr[jj] + w1 * xr[jj + 2] + w2 * xr[jj + 4];
    }

#pragma unroll
    for (int jj = 0; jj < 8; jj++) {
        int j = j0 + base + jj;
        float v = (j < 4094) ? tf32r(acc[jj]) : 0.0f;   // zero-pad tail
        g_V[c2 * NJ + j] = v;
        g_Kt[j * NC + c2] = (c2 < 64) ? v : -v;
    }
}

// ---------------------------------------------------------------------------
// Kernel 2: S1[c] = sum over V row 64+c (pad entries are zero)
// ---------------------------------------------------------------------------
__global__ void __launch_bounds__(256) s1_kernel() {
    __shared__ float red[256];
    const int c = blockIdx.x;
    float s = 0.0f;
    for (int j = threadIdx.x; j < 4096; j += 256) s += g_V[(64 + c) * NJ + j];
    red[threadIdx.x] = s;
    __syncthreads();
    for (int st = 128; st > 0; st >>= 1) {
        if (threadIdx.x < st) red[threadIdx.x] += red[threadIdx.x + st];
        __syncthreads();
    }
    if (threadIdx.x == 0) g_S1[c] = red[0];
}

// ---------------------------------------------------------------------------
// Kernel 3: main kernel. grid 128 = 32 m-tiles(128n) x 4 j-splits(1024 j).
// block 256 = 8 warps = 4m x 2n (R4 tiling: G1 32n x 32j, G2 32n x 64c2).
// smem floats: Qs[128][132] | Ks[64][132] | Vs 2x[128][68] | Ps[128][68]
// Pipeline: [wait0;sync] G1; sigmoid; Pstore; [sync]; commit K(s+1),V(s+1);
// G2.  K single-buffered, V double-buffered.
// ---------------------------------------------------------------------------
#define QS_F 0
#define KS_F 16896
#define VS0_F 25344
#define VS1_F 34048
#define PS_F 42752
#define TOT_F 51456
#define MAIN_SMEM_BYTES (TOT_F * 4)   // 205824

__global__ void __launch_bounds__(256, 1) dspa_main_kernel() {
    extern __shared__ float sm[];
    const uint32_t smb = smem_u32(sm);
    float* Qs = sm + QS_F;
    float* Ks = sm + KS_F;
    float* Ps = sm + PS_F;

    const int tid = threadIdx.x;
    const int warp = tid >> 5, lane = tid & 31;
    const int g = lane >> 2, t = lane & 3;
    const int wm = (warp & 3) * 32;
    const int wn1 = (warp >> 2) * 32;
    const int wn2 = (warp >> 2) * 64;
    const int m0 = (blockIdx.x & 31) << 7;
    const int split = blockIdx.x >> 5;
    const int jb0 = split * JRANGE;

    // ---- prologue: cp.async K(0), V(0); stage Qs; wait; sync ----
#pragma unroll
    for (int i = 0; i < 8; i++) {
        int c = tid + 256 * i;                 // K: 64 rows x 32 float4 chunks
        int row = c >> 5, off = c & 31;
        CP_ASYNC16(smb + KS_F * 4 + row * (132 * 4) + off * 16,
                   (const void*)&g_Kt[(jb0 + row) * NC + off * 4]);
    }
    CP_COMMIT();
#pragma unroll
    for (int i = 0; i < 8; i++) {
        int c = tid + 256 * i;                 // V: 128 rows x 16 chunks
        int row = c >> 4, off = c & 15;
        CP_ASYNC16(smb + VS0_F * 4 + row * (68 * 4) + off * 16,
                   (const void*)&g_V[row * NJ + jb0 + off * 4]);
    }
    CP_COMMIT();
#pragma unroll
    for (int it = 0; it < 16; it++) {
        int idx = it * 256 + tid;              // Q: 128 rows x 32 chunks
        int r = idx >> 5, q = idx & 31;
        float4 v = *reinterpret_cast<const float4*>(&g_Q[(m0 + r) * NC + 4 * q]);
        *reinterpret_cast<float4*>(&Qs[r * 132 + 4 * q]) = v;
    }

    float acc2[16][4];
#pragma unroll
    for (int i = 0; i < 16; i++)
#pragma unroll
        for (int k = 0; k < 4; k++) acc2[i][k] = 0.0f;

    for (int s = 0; s < NSTEPS; s++) {
        float* Vs = sm + ((s & 1) ? VS1_F : VS0_F);

        CP_WAIT0();          // K(s) and V(s) (committed last step) arrived
        __syncthreads();     // also: G2(s-1) done reading V(s-1)/P(s-1)

        // ---- GEMM1: warp computes d[32n x 32j] over c2=128 ----
        float acc1[8][4];
#pragma unroll
        for (int i = 0; i < 8; i++)
#pragma unroll
            for (int k = 0; k < 4; k++) acc1[i][k] = 0.0f;

#pragma unroll
        for (int k0 = 0; k0 < 128; k0 += 8) {
            uint32_t a[2][4];
#pragma unroll
            for (int mt = 0; mt < 2; mt++) {
                const float* q0 = &Qs[(wm + mt * 16 + g) * 132 + k0 + t];
                const float* q1 = q0 + 8 * 132;
                a[mt][0] = __float_as_uint(q0[0]);
                a[mt][1] = __float_as_uint(q1[0]);
                a[mt][2] = __float_as_uint(q0[4]);
                a[mt][3] = __float_as_uint(q1[4]);
            }
#pragma unroll
            for (int nt = 0; nt < 4; nt++) {
                const float* kp = &Ks[(wn1 + nt * 8 + g) * 132 + k0 + t];
                uint32_t b0 = __float_as_uint(kp[0]);
                uint32_t b1 = __float_as_uint(kp[4]);
#pragma unroll
                for (int mt = 0; mt < 2; mt++)
                    mma8(acc1[mt * 4 + nt], a[mt], b0, b1);
            }
        }

        // sigmoid + store P
#pragma unroll
        for (int mt = 0; mt < 2; mt++)
#pragma unroll
            for (int nt = 0; nt < 4; nt++) {
                int rn = wm + mt * 16 + g;
                int cj = wn1 + nt * 8 + 2 * t;
                float* c = acc1[mt * 4 + nt];
                Ps[rn * 68 + cj]           = tf32r(sigf(c[0]));
                Ps[rn * 68 + cj + 1]       = tf32r(sigf(c[1]));
                Ps[(rn + 8) * 68 + cj]     = tf32r(sigf(c[2]));
                Ps[(rn + 8) * 68 + cj + 1] = tf32r(sigf(c[3]));
            }
        __syncthreads();     // P visible; all G1 reads of Ks done

        // prefetch K(s+1) (single buffer, safe now) and V(s+1) (other buffer)
        if (s + 1 < NSTEPS) {
            const int jb = jb0 + (s + 1) * JSTEP;
            uint32_t vdst = smb + (((s + 1) & 1) ? VS1_F : VS0_F) * 4;
#pragma unroll
            for (int i = 0; i < 8; i++) {
                int c = tid + 256 * i;
                int row = c >> 5, off = c & 31;
                CP_ASYNC16(smb + KS_F * 4 + row * (132 * 4) + off * 16,
                           (const void*)&g_Kt[(jb + row) * NC + off * 4]);
            }
            CP_COMMIT();
#pragma unroll
            for (int i = 0; i < 8; i++) {
                int c = tid + 256 * i;
                int row = c >> 4, off = c & 15;
                CP_ASYNC16(vdst + row * (68 * 4) + off * 16,
                           (const void*)&g_V[row * NJ + jb + off * 4]);
            }
            CP_COMMIT();
        }

        // ---- GEMM2: warp accumulates O[32n x 64c2] over j=64 ----
#pragma unroll
        for (int k0 = 0; k0 < 64; k0 += 8) {
            uint32_t a[2][4];
#pragma unroll
            for (int mt = 0; mt < 2; mt++) {
                const float* p0 = &Ps[(wm + mt * 16 + g) * 68 + k0 + t];
                const float* p1 = p0 + 8 * 68;
                a[mt][0] = __float_as_uint(p0[0]);
                a[mt][1] = __float_as_uint(p1[0]);
                a[mt][2] = __float_as_uint(p0[4]);
                a[mt][3] = __float_as_uint(p1[4]);
            }
#pragma unroll
            for (int nt = 0; nt < 8; nt++) {
                const float* vp = &Vs[(wn2 + nt * 8 + g) * 68 + k0 + t];
                uint32_t b0 = __float_as_uint(vp[0]);
                uint32_t b1 = __float_as_uint(vp[4]);
#pragma unroll
                for (int mt = 0; mt < 2; mt++)
                    mma8(acc2[mt * 8 + nt], a[mt], b0, b1);
            }
        }
    }

    // ---- epilogue: fragments -> smem [c2][n] -> coalesced partial stores ----
    __syncthreads();
    float* Osm = sm;   // [128][129] floats, reuses Qs region
#pragma unroll
    for (int mt = 0; mt < 2; mt++)
#pragma unroll
        for (int nt = 0; nt < 8; nt++) {
            int n = wm + mt * 16 + g;
            int c2 = wn2 + nt * 8 + 2 * t;
            const float* c = acc2[mt * 8 + nt];
            Osm[c2 * 129 + n]           = c[0];
            Osm[(c2 + 1) * 129 + n]     = c[1];
            Osm[c2 * 129 + n + 8]       = c[2];
            Osm[(c2 + 1) * 129 + n + 8] = c[3];
        }
    __syncthreads();
#pragma unroll
    for (int it = 0; it < 16; it++) {
        int idx = it * 256 + tid;
        int r = idx >> 5, q = idx & 31;
        float4 v = make_float4(Osm[r * 129 + 4 * q], Osm[r * 129 + 4 * q + 1],
                               Osm[r * 129 + 4 * q + 2], Osm[r * 129 + 4 * q + 3]);
        *reinterpret_cast<float4*>(&g_Op[((split << 7) + r) * NN + m0 + 4 * q]) = v;
    }
}

// ---------------------------------------------------------------------------
// Kernel 4: combine partials + residual + S1 -> out [c2][n]
// ---------------------------------------------------------------------------
__global__ void __launch_bounds__(256) reduce_kernel(const float* __restrict__ x,
                                                     float* __restrict__ out) {
    int idx = blockIdx.x * 256 + threadIdx.x;   // float4 units
    int c2 = idx >> 10;
    const float4* x4 = reinterpret_cast<const float4*>(x);
    const float4* o4 = reinterpret_cast<const float4*>(g_Op);
    float4 xv = x4[idx];
    float4 s = make_float4(0.f, 0.f, 0.f, 0.f);
#pragma unroll
    for (int sp = 0; sp < NSPLIT; sp++) {
        float4 v = o4[((sp << 7) + c2) * (NN / 4) + (idx & 1023)];
        s.x += v.x; s.y += v.y; s.z += v.z; s.w += v.w;
    }
    float4 r;
    if (c2 < 64) {
        r.x = xv.x + s.x; r.y = xv.y + s.y; r.z = xv.z + s.z; r.w = xv.w + s.w;
    } else {
        float b = g_S1[c2 - 64];
        r.x = xv.x + b - s.x; r.y = xv.y + b - s.y;
        r.z = xv.z + b - s.z; r.w = xv.w + b - s.w;
    }
    reinterpret_cast<float4*>(out)[idx] = r;
}

// ---------------------------------------------------------------------------
extern "C" void kernel_launch(void* const* d_in, const int* in_sizes, int n_in,
                              void* d_out, int out_size) {
    const float* x  = (const float*)d_in[0];   // [2,64,16,16,16] = [128][4096]
    const float* cw = (const float*)d_in[1];   // [64,64,3]
    const float* cb = (const float*)d_in[2];   // [64]
    float* out = (float*)d_out;

    cudaFuncSetAttribute(conv_kernel, cudaFuncAttributeMaxDynamicSharedMemorySize, CONV_SMEM_BYTES);
    cudaFuncSetAttribute(dspa_main_kernel, cudaFuncAttributeMaxDynamicSharedMemorySize, MAIN_SMEM_BYTES);

    conv_kernel<<<128, 512, CONV_SMEM_BYTES>>>(x, cw, cb);
    s1_kernel<<<64, 256>>>();
    dspa_main_kernel<<<128, 256, MAIN_SMEM_BYTES>>>();
    reduce_kernel<<<512, 256>>>(x, out);
}